// round 1
// baseline (speedup 1.0000x reference)
#include <cuda_runtime.h>

#define NB 4
#define NS 1024
#define NR 12
#define NDIM 512
#define NH 8
#define ND 64
#define INNER 512
#define NROWS (NB*NS*NR)        /* 49152 */
#define NKV (NS+1)              /* 1025  */
#define LDSIM 1040              /* padded ld for sim/attn */
#define RD (NR*ND)              /* 768   */
#define BH (NB*NH)              /* 32    */

// ---------------- scratch (static device globals; no allocation) ----------------
__device__ float g_xn [(size_t)NROWS * NDIM];        // xn, later reused for pre-LN proj output
__device__ float g_q  [(size_t)BH * NS  * RD];       // q [bh, i, r*64+d]; reused for o [b,n,r,(h d)]
__device__ float g_k  [(size_t)BH * NKV * RD];       // k with null row 0
__device__ float g_v  [(size_t)BH * NKV * RD];
__device__ float g_sim[(size_t)BH * NS  * LDSIM];    // sim -> attn in place

// ---------------- helpers ----------------
__device__ __forceinline__ void ffma2(unsigned long long &c, unsigned long long a,
                                      unsigned long long b) {
    asm("fma.rn.f32x2 %0, %1, %2, %0;" : "+l"(c) : "l"(a), "l"(b));
}

// 128x128 tile inner product over one 16-deep k-slab, packed f32x2 along N.
__device__ __forceinline__ void mm_inner(const float (*As)[128], const float (*Bs)[128],
                                         unsigned long long acc[8][4], int ty, int tx)
{
#pragma unroll
    for (int kk = 0; kk < 16; kk++) {
        float4 va0 = *(const float4*)&As[kk][ty*8];
        float4 va1 = *(const float4*)&As[kk][ty*8+4];
        ulonglong2 vb0 = *(const ulonglong2*)&Bs[kk][tx*8];
        ulonglong2 vb1 = *(const ulonglong2*)&Bs[kk][tx*8+4];
        unsigned long long b2[4] = {vb0.x, vb0.y, vb1.x, vb1.y};
        float a[8] = {va0.x, va0.y, va0.z, va0.w, va1.x, va1.y, va1.z, va1.w};
#pragma unroll
        for (int i = 0; i < 8; i++) {
            unsigned ai = __float_as_uint(a[i]);
            unsigned long long a2;
            asm("mov.b64 %0, {%1, %1};" : "=l"(a2) : "r"(ai));
#pragma unroll
            for (int j = 0; j < 4; j++) ffma2(acc[i][j], a2, b2[j]);
        }
    }
}

__device__ __forceinline__ void unpack_acc(const unsigned long long acc[8][4],
                                           float accf[8][8])
{
#pragma unroll
    for (int i = 0; i < 8; i++)
#pragma unroll
        for (int j = 0; j < 4; j++) {
            accf[i][2*j]   = __uint_as_float((unsigned)(acc[i][j] & 0xffffffffull));
            accf[i][2*j+1] = __uint_as_float((unsigned)(acc[i][j] >> 32));
        }
}

// ---------------- layernorm ----------------
template<int SRC_GLOBAL, int DST_GLOBAL>
__global__ void ln_kernel(const float* __restrict__ xin, const float* __restrict__ g,
                          float* __restrict__ yout)
{
    __shared__ float red1[4], red2[4];
    const float* x = SRC_GLOBAL ? g_xn : xin;
    float*       y = DST_GLOBAL ? g_xn : yout;
    size_t row = blockIdx.x;
    int tid = threadIdx.x;                       // 128 threads, 4 floats each
    float4 v = ((const float4*)(x + row * NDIM))[tid];
    float s = v.x + v.y + v.z + v.w;
#pragma unroll
    for (int o = 16; o; o >>= 1) s += __shfl_xor_sync(0xffffffffu, s, o);
    if ((tid & 31) == 0) red1[tid >> 5] = s;
    __syncthreads();
    float mean = (red1[0] + red1[1] + red1[2] + red1[3]) * (1.0f / NDIM);
    float d0 = v.x - mean, d1 = v.y - mean, d2 = v.z - mean, d3 = v.w - mean;
    float ss = d0*d0 + d1*d1 + d2*d2 + d3*d3;
#pragma unroll
    for (int o = 16; o; o >>= 1) ss += __shfl_xor_sync(0xffffffffu, ss, o);
    if ((tid & 31) == 0) red2[tid >> 5] = ss;
    __syncthreads();
    float var = (red2[0] + red2[1] + red2[2] + red2[3]) * (1.0f / NDIM);
    float inv = rsqrtf(var + 1e-5f);
    float4 gv = ((const float4*)g)[tid];
    float4 o4;
    o4.x = d0 * inv * gv.x; o4.y = d1 * inv * gv.y;
    o4.z = d2 * inv * gv.z; o4.w = d3 * inv * gv.w;
    ((float4*)(y + row * NDIM))[tid] = o4;
}

// ---------------- generic NT GEMM (C = A[MxK] * B[NxK]^T), mode-specialized ----------------
#define GQ 0
#define GKV 1
#define GSIM 2
#define GOPROJ 3

template<int MODE>
__global__ __launch_bounds__(256, 2)
void gemm_nt(const float* __restrict__ Ain, const float* __restrict__ Bin,
             int M, int Nn, int K, int lda, int ldb)
{
    __shared__ float As[16][128];
    __shared__ float Bs[16][128];
    const int tid = threadIdx.x;
    const int m0 = blockIdx.y * 128;
    const int n0 = blockIdx.x * 128;
    const int lr = tid >> 2;
    const int lc = (tid & 3) << 2;
    const int ty = tid >> 4;
    const int tx = tid & 15;

    const float* A;
    const float* Bw;
    if constexpr (MODE == GQ)      { A = g_xn; Bw = Bin; }
    else if constexpr (MODE == GKV){ A = Ain;  Bw = Bin; }
    else if constexpr (MODE == GSIM) {
        size_t z = blockIdx.z;
        A  = g_q + z * (size_t)NS  * RD;
        Bw = g_k + z * (size_t)NKV * RD;
    } else                         { A = g_q;  Bw = Bin; }

    unsigned long long acc[8][4] = {};

    for (int k0 = 0; k0 < K; k0 += 16) {
#pragma unroll
        for (int i = 0; i < 2; i++) {
            int r = lr + i * 64;
            int gm = m0 + r;
            float4 va = make_float4(0.f, 0.f, 0.f, 0.f);
            if (gm < M) va = *(const float4*)(A + (size_t)gm * lda + (k0 + lc));
            As[lc+0][r] = va.x; As[lc+1][r] = va.y; As[lc+2][r] = va.z; As[lc+3][r] = va.w;
            int gn = n0 + r;
            float4 vb = make_float4(0.f, 0.f, 0.f, 0.f);
            if (gn < Nn) vb = *(const float4*)(Bw + (size_t)gn * ldb + (k0 + lc));
            Bs[lc+0][r] = vb.x; Bs[lc+1][r] = vb.y; Bs[lc+2][r] = vb.z; Bs[lc+3][r] = vb.w;
        }
        __syncthreads();
        mm_inner(As, Bs, acc, ty, tx);
        __syncthreads();
    }

    float accf[8][8];
    unpack_acc(acc, accf);

    if constexpr (MODE == GQ) {
        // scale = d^-0.5 / alpha * r^-0.5  (power-of-2 factor exact -> matches fp32 ref scale)
        const float QS = (0.125f / 128.0f) * 0.28867513459481287f;
#pragma unroll
        for (int i = 0; i < 8; i++) {
            int gm = m0 + ty*8 + i;
            int r = gm % NR; int t = gm / NR; int nn = t & (NS - 1); int b = t >> 10;
            size_t base = ((size_t)(b * NH) * NS + nn) * RD + r * ND;
#pragma unroll
            for (int j = 0; j < 8; j++) {
                int e = n0 + tx*8 + j;
                int h = e >> 6, d = e & 63;
                g_q[base + (size_t)h * NS * RD + d] = accf[i][j] * QS;
            }
        }
    } else if constexpr (MODE == GKV) {
#pragma unroll
        for (int i = 0; i < 8; i++) {
            int gm = m0 + ty*8 + i;
            int r = gm % NR; int t = gm / NR; int nn = t & (NS - 1); int b = t >> 10;
            size_t base = ((size_t)(b * NH) * NKV + (nn + 1)) * RD + r * ND;
#pragma unroll
            for (int j = 0; j < 8; j++) {
                int e = n0 + tx*8 + j;
                if (e < INNER) {
                    int h = e >> 6, d = e & 63;
                    g_k[base + (size_t)h * NKV * RD + d] = accf[i][j];
                } else {
                    int e2 = e - INNER;
                    int h = e2 >> 6, d = e2 & 63;
                    g_v[base + (size_t)h * NKV * RD + d] = accf[i][j];
                }
            }
        }
    } else if constexpr (MODE == GSIM) {
        size_t z = blockIdx.z;
        float* Cp = g_sim + z * (size_t)NS * LDSIM;
#pragma unroll
        for (int i = 0; i < 8; i++) {
            int gm = m0 + ty*8 + i;
            float* cr = Cp + (size_t)gm * LDSIM + n0 + tx*8;
            if (n0 + 128 <= Nn) {
                *(float4*)cr     = make_float4(accf[i][0], accf[i][1], accf[i][2], accf[i][3]);
                *(float4*)(cr+4) = make_float4(accf[i][4], accf[i][5], accf[i][6], accf[i][7]);
            } else {
#pragma unroll
                for (int j = 0; j < 8; j++)
                    if (n0 + tx*8 + j < Nn) cr[j] = accf[i][j];
            }
        }
    } else { // GOPROJ: plain [NROWS, 512] into g_xn
#pragma unroll
        for (int i = 0; i < 8; i++) {
            int gm = m0 + ty*8 + i;
            float* cr = g_xn + (size_t)gm * NDIM + n0 + tx*8;
            *(float4*)cr     = make_float4(accf[i][0], accf[i][1], accf[i][2], accf[i][3]);
            *(float4*)(cr+4) = make_float4(accf[i][4], accf[i][5], accf[i][6], accf[i][7]);
        }
    }
}

// ---------------- NN GEMM: out = attn[1024x1040] * v[1025x768], scatter into o ----------------
__global__ __launch_bounds__(256, 2)
void gemm_av()
{
    __shared__ float As[16][128];
    __shared__ float Bs[16][128];
    const int tid = threadIdx.x;
    const int m0 = blockIdx.y * 128;    // i (query) rows
    const int n0 = blockIdx.x * 128;    // rd cols
    const size_t z = blockIdx.z;        // bh
    const float* A  = g_sim + z * (size_t)NS  * LDSIM;
    const float* Bv = g_v   + z * (size_t)NKV * RD;
    const int lr = tid >> 2, lc = (tid & 3) << 2;
    const int br = tid >> 5, bc = (tid & 31) << 2;
    const int ty = tid >> 4, tx = tid & 15;

    unsigned long long acc[8][4] = {};

    for (int k0 = 0; k0 < LDSIM; k0 += 16) {
#pragma unroll
        for (int i = 0; i < 2; i++) {
            int r = lr + i * 64;
            float4 v4 = *(const float4*)(A + (size_t)(m0 + r) * LDSIM + k0 + lc);
            As[lc+0][r] = v4.x; As[lc+1][r] = v4.y; As[lc+2][r] = v4.z; As[lc+3][r] = v4.w;
        }
#pragma unroll
        for (int i = 0; i < 2; i++) {
            int kr = br + i * 8;
            int gk = k0 + kr;
            float4 w4 = make_float4(0.f, 0.f, 0.f, 0.f);
            if (gk < NKV) w4 = *(const float4*)(Bv + (size_t)gk * RD + n0 + bc);
            *(float4*)&Bs[kr][bc] = w4;
        }
        __syncthreads();
        mm_inner(As, Bs, acc, ty, tx);
        __syncthreads();
    }

    float accf[8][8];
    unpack_acc(acc, accf);
    int b = (int)(z >> 3), h = (int)(z & 7);
#pragma unroll
    for (int i = 0; i < 8; i++) {
        int gm = m0 + ty*8 + i;
#pragma unroll
        for (int j = 0; j < 8; j++) {
            int rd = n0 + tx*8 + j;
            int r = rd >> 6, d = rd & 63;
            // o[b, i, r, h*64+d] reusing g_q (q is dead, sizes identical)
            g_q[(((size_t)b * NS + gm) * NR + r) * NDIM + h * ND + d] = accf[i][j];
        }
    }
}

// ---------------- null kv row fill ----------------
__global__ void fill_null(const float* __restrict__ nkv)
{
    int idx = blockIdx.x * blockDim.x + threadIdx.x;
    if (idx >= BH * RD) return;
    int bh = idx / RD;
    int rd = idx % RD;
    int d = rd & 63;
    g_k[(size_t)bh * NKV * RD + rd] = nkv[d];
    g_v[(size_t)bh * NKV * RD + rd] = nkv[64 + d];
}

// ---------------- pb-relax softmax over rows of length 1025 (ld 1040, zero pads) ----------------
__global__ void softmax_kernel()
{
    __shared__ float red[8];
    float* p = g_sim + (size_t)blockIdx.x * LDSIM;
    int tid = threadIdx.x;  // 256
    float vals[5];
    float mx = -1e30f;
#pragma unroll
    for (int it = 0; it < 5; it++) {
        int idx = tid + it * 256;
        float v = (idx < NKV) ? p[idx] : -1e30f;
        vals[it] = v;
        mx = fmaxf(mx, v);
    }
#pragma unroll
    for (int o = 16; o; o >>= 1) mx = fmaxf(mx, __shfl_xor_sync(0xffffffffu, mx, o));
    if ((tid & 31) == 0) red[tid >> 5] = mx;
    __syncthreads();
    float bm = red[0];
#pragma unroll
    for (int w = 1; w < 8; w++) bm = fmaxf(bm, red[w]);
    __syncthreads();
    float s = 0.f;
#pragma unroll
    for (int it = 0; it < 5; it++) {
        int idx = tid + it * 256;
        float e = 0.f;
        if (idx < NKV) e = expf((vals[it] - bm) * 128.0f);
        vals[it] = e;
        s += e;
    }
#pragma unroll
    for (int o = 16; o; o >>= 1) s += __shfl_xor_sync(0xffffffffu, s, o);
    if ((tid & 31) == 0) red[tid >> 5] = s;
    __syncthreads();
    float bs = red[0] + red[1] + red[2] + red[3] + red[4] + red[5] + red[6] + red[7];
    float inv = 1.0f / bs;
#pragma unroll
    for (int it = 0; it < 5; it++) {
        int idx = tid + it * 256;
        if (idx < LDSIM) p[idx] = (idx < NKV) ? vals[it] * inv : 0.f;
    }
}

// ---------------- launch ----------------
extern "C" void kernel_launch(void* const* d_in, const int* in_sizes, int n_in,
                              void* d_out, int out_size)
{
    const float* x         = (const float*)d_in[0];
    const float* context   = (const float*)d_in[1];
    const float* norm_g    = (const float*)d_in[2];
    const float* to_q_w    = (const float*)d_in[3];
    const float* to_kv_w   = (const float*)d_in[4];
    const float* null_kv   = (const float*)d_in[5];
    const float* to_out_w  = (const float*)d_in[6];
    const float* out_ng    = (const float*)d_in[7];
    float* out = (float*)d_out;

    // 1. xn = LN(x, norm_g)
    ln_kernel<0, 1><<<NROWS, 128>>>(x, norm_g, nullptr);
    // 2. q = (xn @ Wq^T) * scale, scattered to [bh, i, r*64+d]
    gemm_nt<GQ><<<dim3(INNER/128, NROWS/128, 1), 256>>>(nullptr, to_q_w,
                                                        NROWS, INNER, NDIM, NDIM, NDIM);
    // 3. k,v = context @ Wkv^T, scattered to [bh, j+1, r*64+d]
    gemm_nt<GKV><<<dim3(2*INNER/128, NROWS/128, 1), 256>>>(context, to_kv_w,
                                                           NROWS, 2*INNER, NDIM, NDIM, NDIM);
    // 4. null kv -> row j=0
    fill_null<<<(BH*RD + 255)/256, 256>>>(null_kv);
    // 5. sim = q @ k^T per bh  (1024 x 1025, ld 1040)
    gemm_nt<GSIM><<<dim3((NKV + 127)/128, NS/128, BH), 256>>>(nullptr, nullptr,
                                                              NS, NKV, RD, RD, RD);
    // 6. pb-relax softmax in place (+ zero pad cols)
    softmax_kernel<<<BH * NS, 256>>>();
    // 7. o = attn @ v, scatter to [b, n, r, (h d)] (reuses g_q)
    gemm_av<<<dim3(RD/128, NS/128, BH), 256>>>();
    // 8. pre-LN out = o @ Wout^T -> g_xn
    gemm_nt<GOPROJ><<<dim3(NDIM/128, NROWS/128, 1), 256>>>(nullptr, to_out_w,
                                                           NROWS, NDIM, INNER, INNER, INNER);
    // 9. final LN -> d_out
    ln_kernel<1, 0><<<NROWS, 128>>>(nullptr, out_ng, out);
    (void)in_sizes; (void)n_in; (void)out_size;
}

// round 3
// speedup vs baseline: 1.0604x; 1.0604x over previous
#include <cuda_runtime.h>

#define NB 4
#define NS 1024
#define NR 12
#define NDIM 512
#define NH 8
#define ND 64
#define INNER 512
#define NROWS (NB*NS*NR)        /* 49152 */
#define NKV (NS+1)              /* 1025  */
#define LDSIM 1040              /* padded ld for sim/attn */
#define RD (NR*ND)              /* 768   */
#define BH (NB*NH)              /* 32    */

// smem tile strides (floats). LDAD = duplicated-A row stride, LDBS = B row stride.
#define LDAD 260
#define LDBS 132
#define STAGE_F (16*LDAD + 16*LDBS)          /* 6272 floats per stage */
#define GEMM_SMEM_BYTES (2*STAGE_F*4)        /* 50176 bytes */

// ---------------- scratch (static device globals; no allocation) ----------------
__device__ float g_xn [(size_t)NROWS * NDIM];
__device__ float g_q  [(size_t)BH * NS  * RD];       // q; reused for o [b,n,r,(h d)]
__device__ float g_k  [(size_t)BH * NKV * RD];
__device__ float g_v  [(size_t)BH * NKV * RD];
__device__ float g_sim[(size_t)BH * NS  * LDSIM];

// ---------------- helpers ----------------
__device__ __forceinline__ void ffma2(unsigned long long &c, unsigned long long a,
                                      unsigned long long b) {
    asm("fma.rn.f32x2 %0, %1, %2, %0;" : "+l"(c) : "l"(a), "l"(b));
}

// store one k-slab (held in registers) into smem stage: A duplicated+transposed, B transposed
__device__ __forceinline__ void sts_nt(float* st, int lr, int lc,
                                       const float4& pa0, const float4& pa1,
                                       const float4& pb0, const float4& pb1)
{
    float* as = st;
    float* bs = st + 16*LDAD;
#pragma unroll
    for (int j = 0; j < 4; j++) {
        float v0 = (&pa0.x)[j];
        float v1 = (&pa1.x)[j];
        *(float2*)&as[(lc+j)*LDAD + 2*lr]        = make_float2(v0, v0);
        *(float2*)&as[(lc+j)*LDAD + 2*(lr+64)]   = make_float2(v1, v1);
        bs[(lc+j)*LDBS + lr]      = (&pb0.x)[j];
        bs[(lc+j)*LDBS + lr + 64] = (&pb1.x)[j];
    }
}

// 128x128 x 16-deep inner product, packed f32x2 along n, A pre-duplicated in smem
__device__ __forceinline__ void compute16(const float* st, int wm, int wn, int lm, int ln,
                                          unsigned long long (&acc)[2][4][2][2])
{
    const float* as = st + (wm*32 + lm*4)*2;
    const float* bs = st + 16*LDAD + wn*64 + ln*4;
#pragma unroll
    for (int kk = 0; kk < 16; kk++) {
        ulonglong2 a00 = *(const ulonglong2*)(as + kk*LDAD);
        ulonglong2 a01 = *(const ulonglong2*)(as + kk*LDAD + 4);
        ulonglong2 a10 = *(const ulonglong2*)(as + kk*LDAD + 32);
        ulonglong2 a11 = *(const ulonglong2*)(as + kk*LDAD + 36);
        ulonglong2 b0  = *(const ulonglong2*)(bs + kk*LDBS);
        ulonglong2 b1  = *(const ulonglong2*)(bs + kk*LDBS + 32);
        unsigned long long av[2][4] = {{a00.x, a00.y, a01.x, a01.y},
                                       {a10.x, a10.y, a11.x, a11.y}};
        unsigned long long bv[2][2] = {{b0.x, b0.y}, {b1.x, b1.y}};
#pragma unroll
        for (int cm = 0; cm < 2; cm++)
#pragma unroll
            for (int i = 0; i < 4; i++)
#pragma unroll
                for (int cn = 0; cn < 2; cn++)
#pragma unroll
                    for (int p = 0; p < 2; p++)
                        ffma2(acc[cm][i][cn][p], av[cm][i], bv[cn][p]);
    }
}

__device__ __forceinline__ void unpack8(const unsigned long long (&acc)[2][4][2][2],
                                        float (&vf)[2][4][2][4])
{
#pragma unroll
    for (int cm = 0; cm < 2; cm++)
#pragma unroll
        for (int i = 0; i < 4; i++)
#pragma unroll
            for (int cn = 0; cn < 2; cn++)
#pragma unroll
                for (int p = 0; p < 2; p++) {
                    vf[cm][i][cn][2*p]   = __uint_as_float((unsigned)(acc[cm][i][cn][p] & 0xffffffffull));
                    vf[cm][i][cn][2*p+1] = __uint_as_float((unsigned)(acc[cm][i][cn][p] >> 32));
                }
}

// ---------------- layernorm ----------------
template<int SRC_GLOBAL, int DST_GLOBAL>
__global__ void ln_kernel(const float* __restrict__ xin, const float* __restrict__ g,
                          float* __restrict__ yout)
{
    __shared__ float red1[4], red2[4];
    const float* x = SRC_GLOBAL ? g_xn : xin;
    float*       y = DST_GLOBAL ? g_xn : yout;
    size_t row = blockIdx.x;
    int tid = threadIdx.x;
    float4 v = ((const float4*)(x + row * NDIM))[tid];
    float s = v.x + v.y + v.z + v.w;
#pragma unroll
    for (int o = 16; o; o >>= 1) s += __shfl_xor_sync(0xffffffffu, s, o);
    if ((tid & 31) == 0) red1[tid >> 5] = s;
    __syncthreads();
    float mean = (red1[0] + red1[1] + red1[2] + red1[3]) * (1.0f / NDIM);
    float d0 = v.x - mean, d1 = v.y - mean, d2 = v.z - mean, d3 = v.w - mean;
    float ss = d0*d0 + d1*d1 + d2*d2 + d3*d3;
#pragma unroll
    for (int o = 16; o; o >>= 1) ss += __shfl_xor_sync(0xffffffffu, ss, o);
    if ((tid & 31) == 0) red2[tid >> 5] = ss;
    __syncthreads();
    float var = (red2[0] + red2[1] + red2[2] + red2[3]) * (1.0f / NDIM);
    float inv = rsqrtf(var + 1e-5f);
    float4 gv = ((const float4*)g)[tid];
    float4 o4;
    o4.x = d0 * inv * gv.x; o4.y = d1 * inv * gv.y;
    o4.z = d2 * inv * gv.z; o4.w = d3 * inv * gv.w;
    ((float4*)(y + row * NDIM))[tid] = o4;
}

// ---------------- NT GEMM (C = A[MxK] * B[NxK]^T), mode-specialized ----------------
#define GQ 0
#define GKV 1
#define GSIM 2
#define GOPROJ 3

template<int MODE>
__global__ __launch_bounds__(256, 2)
void gemm_nt(const float* __restrict__ Ain, const float* __restrict__ Bin,
             int M, int Nn, int K, int lda, int ldb)
{
    extern __shared__ float sm[];
    const int tid = threadIdx.x;
    const int m0 = blockIdx.y * 128;
    const int n0 = blockIdx.x * 128;
    const int lane = tid & 31, wid = tid >> 5;
    const int wm = wid & 3, wn = wid >> 2;        // 4 x 2 warp grid, warp tile 32m x 64n
    const int lm = lane >> 3, ln = lane & 7;
    const int lr = tid >> 2, lc = (tid & 3) << 2;

    const float* A;
    const float* Bw;
    if constexpr (MODE == GQ)      { A = g_xn; Bw = Bin; }
    else if constexpr (MODE == GKV){ A = Ain;  Bw = Bin; }
    else if constexpr (MODE == GSIM) {
        size_t z = blockIdx.z;
        A  = g_q + z * (size_t)NS  * RD;
        Bw = g_k + z * (size_t)NKV * RD;
    } else                         { A = g_q;  Bw = Bin; }

    unsigned long long acc[2][4][2][2] = {};
    float4 pa0, pa1, pb0, pb1;
    const float4 z4 = make_float4(0.f, 0.f, 0.f, 0.f);

    // prologue: slab 0 -> regs -> stage 0
    {
        const float* ap = A + (size_t)(m0 + lr) * lda + lc;
        pa0 = *(const float4*)ap;
        pa1 = *(const float4*)(ap + (size_t)64 * lda);
        int gn0 = n0 + lr, gn1 = n0 + lr + 64;
        pb0 = (gn0 < Nn) ? *(const float4*)(Bw + (size_t)gn0 * ldb + lc) : z4;
        pb1 = (gn1 < Nn) ? *(const float4*)(Bw + (size_t)gn1 * ldb + lc) : z4;
    }
    sts_nt(sm, lr, lc, pa0, pa1, pb0, pb1);
    __syncthreads();

    const int nslab = K >> 4;
    for (int s = 0; s < nslab; s++) {
        if (s + 1 < nslab) {
            int k0 = (s + 1) << 4;
            const float* ap = A + (size_t)(m0 + lr) * lda + k0 + lc;
            pa0 = *(const float4*)ap;
            pa1 = *(const float4*)(ap + (size_t)64 * lda);
            int gn0 = n0 + lr, gn1 = n0 + lr + 64;
            pb0 = (gn0 < Nn) ? *(const float4*)(Bw + (size_t)gn0 * ldb + k0 + lc) : z4;
            pb1 = (gn1 < Nn) ? *(const float4*)(Bw + (size_t)gn1 * ldb + k0 + lc) : z4;
        }
        compute16(sm + (s & 1) * STAGE_F, wm, wn, lm, ln, acc);
        __syncthreads();
        if (s + 1 < nslab) {
            sts_nt(sm + ((s + 1) & 1) * STAGE_F, lr, lc, pa0, pa1, pb0, pb1);
            __syncthreads();
        }
    }

    float vf[2][4][2][4];
    unpack8(acc, vf);

#pragma unroll
    for (int cm = 0; cm < 2; cm++)
#pragma unroll
    for (int i = 0; i < 4; i++) {
        int gm = m0 + wm*32 + cm*16 + lm*4 + i;
#pragma unroll
        for (int cn = 0; cn < 2; cn++) {
            int nb = n0 + wn*64 + cn*32 + ln*4;
            float4 v = make_float4(vf[cm][i][cn][0], vf[cm][i][cn][1],
                                   vf[cm][i][cn][2], vf[cm][i][cn][3]);
            if constexpr (MODE == GQ) {
                const float QS = (0.125f / 128.0f) * 0.28867513459481287f;
                v.x *= QS; v.y *= QS; v.z *= QS; v.w *= QS;
                int r = gm % NR; int t = gm / NR; int nn = t & (NS - 1); int b = t >> 10;
                int h = nb >> 6, d0 = nb & 63;
                float* dst = g_q + ((size_t)(b * NH + h) * NS + nn) * RD + r * ND + d0;
                *(float4*)dst = v;
            } else if constexpr (MODE == GKV) {
                int r = gm % NR; int t = gm / NR; int nn = t & (NS - 1); int b = t >> 10;
                if (nb < INNER) {
                    int h = nb >> 6, d0 = nb & 63;
                    float* dst = g_k + ((size_t)(b * NH + h) * NKV + (nn + 1)) * RD + r * ND + d0;
                    *(float4*)dst = v;
                } else {
                    int e = nb - INNER;
                    int h = e >> 6, d0 = e & 63;
                    float* dst = g_v + ((size_t)(b * NH + h) * NKV + (nn + 1)) * RD + r * ND + d0;
                    *(float4*)dst = v;
                }
            } else if constexpr (MODE == GSIM) {
                size_t zz = blockIdx.z;
                float* cr = g_sim + zz * (size_t)NS * LDSIM + (size_t)gm * LDSIM + nb;
                if (nb + 3 < Nn) {
                    *(float4*)cr = v;
                } else {
#pragma unroll
                    for (int j = 0; j < 4; j++)
                        if (nb + j < Nn) cr[j] = (&v.x)[j];
                }
            } else { // GOPROJ
                float* cr = g_xn + (size_t)gm * NDIM + nb;
                *(float4*)cr = v;
            }
        }
    }
}

// ---------------- NN GEMM: out = attn[1024x1040] * v[1025x768], scatter into o ----------------
__global__ __launch_bounds__(256, 2)
void gemm_av()
{
    extern __shared__ float sm[];
    const int tid = threadIdx.x;
    const int m0 = blockIdx.y * 128;
    const int n0 = blockIdx.x * 128;
    const size_t z = blockIdx.z;
    const float* A  = g_sim + z * (size_t)NS  * LDSIM;
    const float* Bv = g_v   + z * (size_t)NKV * RD;
    const int lane = tid & 31, wid = tid >> 5;
    const int wm = wid & 3, wn = wid >> 2;
    const int lm = lane >> 3, ln = lane & 7;
    const int lr = tid >> 2, lc = (tid & 3) << 2;
    const int kr = tid >> 4, kc = (tid & 15) << 3;   // B loader: one k-row, 8 cols / thread

    unsigned long long acc[2][4][2][2] = {};
    float4 pa0, pa1, pb0, pb1;
    const float4 z4 = make_float4(0.f, 0.f, 0.f, 0.f);

    auto ldr = [&](int k0) {
        const float* ap = A + (size_t)(m0 + lr) * LDSIM + k0 + lc;
        pa0 = *(const float4*)ap;
        pa1 = *(const float4*)(ap + (size_t)64 * LDSIM);
        int gk = k0 + kr;
        if (gk < NKV) {
            const float* bp = Bv + (size_t)gk * RD + n0 + kc;
            pb0 = *(const float4*)bp;
            pb1 = *(const float4*)(bp + 4);
        } else { pb0 = z4; pb1 = z4; }
    };
    auto sts = [&](float* st) {
        float* as = st;
        float* bs = st + 16*LDAD;
#pragma unroll
        for (int j = 0; j < 4; j++) {
            float v0 = (&pa0.x)[j];
            float v1 = (&pa1.x)[j];
            *(float2*)&as[(lc+j)*LDAD + 2*lr]      = make_float2(v0, v0);
            *(float2*)&as[(lc+j)*LDAD + 2*(lr+64)] = make_float2(v1, v1);
        }
        *(float4*)&bs[kr*LDBS + kc]     = pb0;
        *(float4*)&bs[kr*LDBS + kc + 4] = pb1;
    };

    ldr(0);
    sts(sm);
    __syncthreads();

    const int nslab = LDSIM >> 4;   // 65
    for (int s = 0; s < nslab; s++) {
        if (s + 1 < nslab) ldr((s + 1) << 4);
        compute16(sm + (s & 1) * STAGE_F, wm, wn, lm, ln, acc);
        __syncthreads();
        if (s + 1 < nslab) {
            sts(sm + ((s + 1) & 1) * STAGE_F);
            __syncthreads();
        }
    }

    float vf[2][4][2][4];
    unpack8(acc, vf);
    int b = (int)(z >> 3), h = (int)(z & 7);
#pragma unroll
    for (int cm = 0; cm < 2; cm++)
#pragma unroll
    for (int i = 0; i < 4; i++) {
        int gm = m0 + wm*32 + cm*16 + lm*4 + i;
#pragma unroll
        for (int cn = 0; cn < 2; cn++) {
            int nb = n0 + wn*64 + cn*32 + ln*4;
            int r = nb >> 6, d0 = nb & 63;
            float4 v = make_float4(vf[cm][i][cn][0], vf[cm][i][cn][1],
                                   vf[cm][i][cn][2], vf[cm][i][cn][3]);
            float* dst = g_q + (((size_t)b * NS + gm) * NR + r) * NDIM + h * ND + d0;
            *(float4*)dst = v;
        }
    }
}

// ---------------- null kv row fill ----------------
__global__ void fill_null(const float* __restrict__ nkv)
{
    int idx = blockIdx.x * blockDim.x + threadIdx.x;
    if (idx >= BH * RD) return;
    int bh = idx / RD;
    int rd = idx % RD;
    int d = rd & 63;
    g_k[(size_t)bh * NKV * RD + rd] = nkv[d];
    g_v[(size_t)bh * NKV * RD + rd] = nkv[64 + d];
}

// ---------------- pb-relax softmax over rows of length 1025 (ld 1040, zero pads) ----------------
__global__ void softmax_kernel()
{
    __shared__ float red[8];
    float* p = g_sim + (size_t)blockIdx.x * LDSIM;
    int tid = threadIdx.x;  // 256
    float vals[5];
    float mx = -1e30f;
#pragma unroll
    for (int it = 0; it < 5; it++) {
        int idx = tid + it * 256;
        float v = (idx < NKV) ? p[idx] : -1e30f;
        vals[it] = v;
        mx = fmaxf(mx, v);
    }
#pragma unroll
    for (int o = 16; o; o >>= 1) mx = fmaxf(mx, __shfl_xor_sync(0xffffffffu, mx, o));
    if ((tid & 31) == 0) red[tid >> 5] = mx;
    __syncthreads();
    float bm = red[0];
#pragma unroll
    for (int w = 1; w < 8; w++) bm = fmaxf(bm, red[w]);
    __syncthreads();
    float s = 0.f;
#pragma unroll
    for (int it = 0; it < 5; it++) {
        int idx = tid + it * 256;
        float e = 0.f;
        if (idx < NKV) e = expf((vals[it] - bm) * 128.0f);
        vals[it] = e;
        s += e;
    }
#pragma unroll
    for (int o = 16; o; o >>= 1) s += __shfl_xor_sync(0xffffffffu, s, o);
    if ((tid & 31) == 0) red[tid >> 5] = s;
    __syncthreads();
    float bs = red[0] + red[1] + red[2] + red[3] + red[4] + red[5] + red[6] + red[7];
    float inv = 1.0f / bs;
#pragma unroll
    for (int it = 0; it < 5; it++) {
        int idx = tid + it * 256;
        if (idx < LDSIM) p[idx] = (idx < NKV) ? vals[it] * inv : 0.f;
    }
}

// ---------------- launch ----------------
extern "C" void kernel_launch(void* const* d_in, const int* in_sizes, int n_in,
                              void* d_out, int out_size)
{
    const float* x         = (const float*)d_in[0];
    const float* context   = (const float*)d_in[1];
    const float* norm_g    = (const float*)d_in[2];
    const float* to_q_w    = (const float*)d_in[3];
    const float* to_kv_w   = (const float*)d_in[4];
    const float* null_kv   = (const float*)d_in[5];
    const float* to_out_w  = (const float*)d_in[6];
    const float* out_ng    = (const float*)d_in[7];
    float* out = (float*)d_out;

    static bool attr_done = false;
    if (!attr_done) {
        cudaFuncSetAttribute(gemm_nt<GQ>,    cudaFuncAttributeMaxDynamicSharedMemorySize, GEMM_SMEM_BYTES);
        cudaFuncSetAttribute(gemm_nt<GKV>,   cudaFuncAttributeMaxDynamicSharedMemorySize, GEMM_SMEM_BYTES);
        cudaFuncSetAttribute(gemm_nt<GSIM>,  cudaFuncAttributeMaxDynamicSharedMemorySize, GEMM_SMEM_BYTES);
        cudaFuncSetAttribute(gemm_nt<GOPROJ>,cudaFuncAttributeMaxDynamicSharedMemorySize, GEMM_SMEM_BYTES);
        cudaFuncSetAttribute(gemm_av,        cudaFuncAttributeMaxDynamicSharedMemorySize, GEMM_SMEM_BYTES);
        attr_done = true;
    }

    // 1. xn = LN(x, norm_g)
    ln_kernel<0, 1><<<NROWS, 128>>>(x, norm_g, nullptr);
    // 2. q = (xn @ Wq^T) * scale -> [bh, i, r*64+d]
    gemm_nt<GQ><<<dim3(INNER/128, NROWS/128, 1), 256, GEMM_SMEM_BYTES>>>(
        nullptr, to_q_w, NROWS, INNER, NDIM, NDIM, NDIM);
    // 3. k,v = context @ Wkv^T -> [bh, j+1, r*64+d]
    gemm_nt<GKV><<<dim3(2*INNER/128, NROWS/128, 1), 256, GEMM_SMEM_BYTES>>>(
        context, to_kv_w, NROWS, 2*INNER, NDIM, NDIM, NDIM);
    // 4. null kv -> row j=0
    fill_null<<<(BH*RD + 255)/256, 256>>>(null_kv);
    // 5. sim = q @ k^T per bh (1024 x 1025, ld 1040)
    gemm_nt<GSIM><<<dim3((NKV + 127)/128, NS/128, BH), 256, GEMM_SMEM_BYTES>>>(
        nullptr, nullptr, NS, NKV, RD, RD, RD);
    // 6. pb-relax softmax in place (+ zero pad cols)
    softmax_kernel<<<BH * NS, 256>>>();
    // 7. o = attn @ v -> [b, n, r, (h d)] (reuses g_q)
    gemm_av<<<dim3(RD/128, NS/128, BH), 256, GEMM_SMEM_BYTES>>>();
    // 8. pre-LN out = o @ Wout^T -> g_xn
    gemm_nt<GOPROJ><<<dim3(NDIM/128, NROWS/128, 1), 256, GEMM_SMEM_BYTES>>>(
        nullptr, to_out_w, NROWS, NDIM, INNER, INNER, INNER);
    // 9. final LN -> d_out
    ln_kernel<1, 0><<<NROWS, 128>>>(nullptr, out_ng, out);
    (void)in_sizes; (void)n_in; (void)out_size;
}

// round 5
// speedup vs baseline: 2.0357x; 1.9198x over previous
#include <cuda_runtime.h>
#include <cuda_fp16.h>
#include <cstdint>

#define NB 4
#define NS 1024
#define NR 12
#define NDIM 512
#define NH 8
#define ND 64
#define NROWS (NB*NS*NR)        /* 49152 */
#define NKV (NS+1)              /* 1025  */
#define LDSIM 1040              /* fp32 sim ld */
#define LDAT 1056               /* fp16 attn / v_t ld (mult of 32) */
#define RD (NR*ND)              /* 768 */
#define BH (NB*NH)              /* 32 */

// smem: per stage, A 128x40 halves + B 128x40 halves
#define LDS 40
#define ASTG (128*LDS)              /* 5120 halves */
#define STG  (2*ASTG)               /* 10240 halves per stage */
#define GEMM_SMEM (2*STG*2)         /* 40960 bytes */

// ---------------- scratch ----------------
__device__ __half g_xnh [(size_t)NROWS * NDIM];
__device__ __half g_xnl [(size_t)NROWS * NDIM];
__device__ __half g_ctxh[(size_t)NROWS * NDIM];
__device__ __half g_ctxl[(size_t)NROWS * NDIM];
__device__ __half g_wqh [512*512],  g_wql [512*512];
__device__ __half g_wkvh[1024*512], g_wkvl[1024*512];
__device__ __half g_woh [512*512],  g_wol [512*512];
__device__ __half g_qh  [(size_t)BH * NS * RD];
__device__ __half g_ql  [(size_t)BH * NS * RD];
__device__ __half g_kh  [(size_t)BH * NKV * RD];
__device__ __half g_kl  [(size_t)BH * NKV * RD];
__device__ float  g_vf  [(size_t)BH * NKV * RD];
__device__ __half g_vth [(size_t)BH * RD * LDAT];
__device__ __half g_vtl [(size_t)BH * RD * LDAT];
__device__ float  g_sim [(size_t)BH * NS * LDSIM];
__device__ __half g_ath [(size_t)BH * NS * LDAT];
__device__ __half g_atl [(size_t)BH * NS * LDAT];
__device__ __half g_oh  [(size_t)NROWS * NDIM];
__device__ __half g_ol  [(size_t)NROWS * NDIM];
__device__ float  g_out [(size_t)NROWS * NDIM];

// ---------------- helpers ----------------
__device__ __forceinline__ uint32_t smem_u32(const void* p) {
    uint32_t a;
    asm("{ .reg .u64 t; cvta.to.shared.u64 t, %1; cvt.u32.u64 %0, t; }" : "=r"(a) : "l"(p));
    return a;
}
__device__ __forceinline__ void ldsm4(uint32_t* r, uint32_t addr) {
    asm volatile("ldmatrix.sync.aligned.m8n8.x4.shared.b16 {%0,%1,%2,%3}, [%4];"
                 : "=r"(r[0]), "=r"(r[1]), "=r"(r[2]), "=r"(r[3]) : "r"(addr));
}
__device__ __forceinline__ void mma16816(float* c, const uint32_t* a, uint32_t b0, uint32_t b1) {
    asm volatile("mma.sync.aligned.m16n8k16.row.col.f32.f16.f16.f32 "
                 "{%0,%1,%2,%3}, {%4,%5,%6,%7}, {%8,%9}, {%0,%1,%2,%3};"
                 : "+f"(c[0]), "+f"(c[1]), "+f"(c[2]), "+f"(c[3])
                 : "r"(a[0]), "r"(a[1]), "r"(a[2]), "r"(a[3]), "r"(b0), "r"(b1));
}
__device__ __forceinline__ uint32_t pk_hi(float a, float b) {
    __half2 t = __floats2half2_rn(a, b);
    return *(uint32_t*)&t;
}
__device__ __forceinline__ uint32_t pk_lo(float a, float b) {
    float ha = __half2float(__float2half_rn(a));
    float hb = __half2float(__float2half_rn(b));
    __half2 t = __floats2half2_rn(a - ha, b - hb);
    return *(uint32_t*)&t;
}
__device__ __forceinline__ void split1(float v, __half* ph, __half* pl) {
    __half h = __float2half_rn(v);
    *ph = h; *pl = __float2half_rn(v - __half2float(h));
}

// ---------------- HMMA GEMM: D[m,n] = sum_k A[m,k]*B[n,k] (fp16 hi/lo triple-K) ----------
#define GQPROJ 0
#define GKVPROJ 1
#define GSIM 2
#define GAV 3
#define GOPROJ 4

template<int MODE>
__global__ __launch_bounds__(256, 2) void gemm_hmma()
{
    extern __shared__ __half sh[];
    const int tid = threadIdx.x, lane = tid & 31, wid = tid >> 5;
    const int m0 = blockIdx.y * 128, n0 = blockIdx.x * 128;

    constexpr int Nn  = MODE==GQPROJ ? 512 : MODE==GKVPROJ ? 1024 :
                        MODE==GSIM ? NKV : MODE==GAV ? RD : 512;
    constexpr int K   = MODE==GSIM ? RD : MODE==GAV ? LDAT : 512;
    constexpr int lda = K;
    constexpr int ldb = K;
    constexpr int SPR = K / 32;
    constexpr int S   = 3 * SPR;

    const __half *Ah, *Al, *Bh, *Bl;
    if constexpr (MODE == GQPROJ)      { Ah=g_xnh;  Al=g_xnl;  Bh=g_wqh;  Bl=g_wql; }
    else if constexpr (MODE == GKVPROJ){ Ah=g_ctxh; Al=g_ctxl; Bh=g_wkvh; Bl=g_wkvl; }
    else if constexpr (MODE == GSIM) {
        size_t z = blockIdx.z;
        Ah=g_qh + z*(size_t)NS*RD;   Al=g_ql + z*(size_t)NS*RD;
        Bh=g_kh + z*(size_t)NKV*RD;  Bl=g_kl + z*(size_t)NKV*RD;
    } else if constexpr (MODE == GAV) {
        size_t z = blockIdx.z;
        Ah=g_ath + z*(size_t)NS*LDAT; Al=g_atl + z*(size_t)NS*LDAT;
        Bh=g_vth + z*(size_t)RD*LDAT; Bl=g_vtl + z*(size_t)RD*LDAT;
    } else                             { Ah=g_oh;   Al=g_ol;   Bh=g_woh;  Bl=g_wol; }

    // warp tiling: 2 (m) x 4 (n); warp tile 64m x 32n
    const int m0w = (wid & 1) * 64;
    const int n0w = (wid >> 1) * 32;

    // loader: A 512 uint4 (128 rows x 4 chunks), B same; 2 per thread each
    const int lrow = tid >> 2;              // 0..63
    const int lc   = (tid & 3) * 8;         // half offset within 32

    // ldmatrix lane base addresses (bytes into smem)
    const uint32_t smb = smem_u32(sh);
    const uint32_t aAddr = smb + (uint32_t)(((m0w + (lane & 15)) * LDS + ((lane >> 4) << 3)) * 2);
    const uint32_t bAddr = smb + (uint32_t)((ASTG + (n0w + (lane & 15)) * LDS + ((lane >> 4) << 3)) * 2);

    float acc[4][4][4] = {};
    uint4 pa0, pa1, pb0, pb1;

    auto ldslab = [&](int s) {
        const int rg = s / SPR;
        const int k0 = (s - rg * SPR) * 32;
        const __half* Ap = (rg == 1) ? Al : Ah;
        const __half* Bp = (rg == 2) ? Bl : Bh;
        pa0 = *(const uint4*)(Ap + (size_t)(m0 + lrow)      * lda + k0 + lc);
        pa1 = *(const uint4*)(Ap + (size_t)(m0 + lrow + 64) * lda + k0 + lc);
        const uint4 z4 = make_uint4(0u,0u,0u,0u);
        pb0 = (n0 + lrow      < Nn) ? *(const uint4*)(Bp + (size_t)(n0 + lrow)      * ldb + k0 + lc) : z4;
        pb1 = (n0 + lrow + 64 < Nn) ? *(const uint4*)(Bp + (size_t)(n0 + lrow + 64) * ldb + k0 + lc) : z4;
    };
    auto stslab = [&](int buf) {
        __half* st = sh + buf * STG;
        *(uint4*)(st + lrow * LDS + lc)        = pa0;
        *(uint4*)(st + (lrow + 64) * LDS + lc) = pa1;
        *(uint4*)(st + ASTG + lrow * LDS + lc)        = pb0;
        *(uint4*)(st + ASTG + (lrow + 64) * LDS + lc) = pb1;
    };
    auto compute = [&](int buf) {
        const uint32_t aB = aAddr + buf * (STG * 2);
        const uint32_t bB = bAddr + buf * (STG * 2);
#pragma unroll
        for (int k16 = 0; k16 < 2; k16++) {
            uint32_t a[4][4], b[2][4];
#pragma unroll
            for (int mf = 0; mf < 4; mf++) ldsm4(a[mf], aB + mf * (16*LDS*2) + k16 * 32);
#pragma unroll
            for (int nf = 0; nf < 2; nf++) ldsm4(b[nf], bB + nf * (16*LDS*2) + k16 * 32);
#pragma unroll
            for (int mf = 0; mf < 4; mf++)
#pragma unroll
                for (int j = 0; j < 4; j++)
                    mma16816(acc[mf][j], a[mf], b[j>>1][j&1], b[j>>1][(j&1)+2]);
        }
    };

    ldslab(0);
    stslab(0);
    __syncthreads();
    for (int s = 0; s < S; s++) {
        if (s + 1 < S) ldslab(s + 1);
        compute(s & 1);
        __syncthreads();
        if (s + 1 < S) {
            stslab((s + 1) & 1);
            __syncthreads();
        }
    }

    // epilogue: acc[mf][j][{d0,d1,d2,d3}]:
    // rows gm = m0+m0w+mf*16+(lane>>2) (+8 for d2,d3); cols gn = n0+n0w+j*8+(lane&3)*2 (+1)
    const int rbase = m0 + m0w + (lane >> 2);
    const int cbase = n0 + n0w + (lane & 3) * 2;
#pragma unroll
    for (int mf = 0; mf < 4; mf++)
#pragma unroll
    for (int half = 0; half < 2; half++) {
        const int gm = rbase + mf * 16 + half * 8;
#pragma unroll
        for (int j = 0; j < 4; j++) {
            const int gn = cbase + j * 8;
            const float v0 = acc[mf][j][half * 2 + 0];
            const float v1 = acc[mf][j][half * 2 + 1];
            if constexpr (MODE == GQPROJ) {
                int rr = gm % NR, t = gm / NR; int nn = t & (NS-1); int b = t >> 10;
                int h = gn >> 6, d = gn & 63;
                size_t off = ((size_t)((b << 3) + h) * NS + nn) * RD + rr * ND + d;
                *(uint32_t*)(g_qh + off) = pk_hi(v0, v1);
                *(uint32_t*)(g_ql + off) = pk_lo(v0, v1);
            } else if constexpr (MODE == GKVPROJ) {
                int rr = gm % NR, t = gm / NR; int nn = t & (NS-1); int b = t >> 10;
                if (gn < 512) {
                    int h = gn >> 6, d = gn & 63;
                    size_t off = ((size_t)((b << 3) + h) * NKV + nn + 1) * RD + rr * ND + d;
                    *(uint32_t*)(g_kh + off) = pk_hi(v0, v1);
                    *(uint32_t*)(g_kl + off) = pk_lo(v0, v1);
                } else {
                    int e = gn - 512; int h = e >> 6, d = e & 63;
                    size_t off = ((size_t)((b << 3) + h) * NKV + nn + 1) * RD + rr * ND + d;
                    *(float2*)(g_vf + off) = make_float2(v0, v1);
                }
            } else if constexpr (MODE == GSIM) {
                const float QS = (0.125f / 128.0f) * 0.28867513459481287f;
                size_t z = blockIdx.z;
                float* cr = g_sim + (z * NS + gm) * (size_t)LDSIM + gn;
                if (gn + 1 < NKV)      *(float2*)cr = make_float2(v0 * QS, v1 * QS);
                else if (gn < NKV)     cr[0] = v0 * QS;
            } else if constexpr (MODE == GAV) {
                size_t z = blockIdx.z; int b = (int)(z >> 3), h = (int)(z & 7);
                int rr = gn >> 6, d = gn & 63;
                size_t off = (((size_t)b * NS + gm) * NR + rr) * NDIM + h * ND + d;
                *(uint32_t*)(g_oh + off) = pk_hi(v0, v1);
                *(uint32_t*)(g_ol + off) = pk_lo(v0, v1);
            } else {
                *(float2*)(g_out + (size_t)gm * NDIM + gn) = make_float2(v0, v1);
            }
        }
    }
}

// ---------------- fp32 -> hi/lo fp16 ----------------
__global__ void conv_hilo(const float* __restrict__ src,
                          __half* __restrict__ hi, __half* __restrict__ lo, int n4)
{
    int i = blockIdx.x * 256 + threadIdx.x;
    if (i >= n4) return;
    float4 v = ((const float4*)src)[i];
    *(uint2*)(hi + 4*(size_t)i) = make_uint2(pk_hi(v.x, v.y), pk_hi(v.z, v.w));
    *(uint2*)(lo + 4*(size_t)i) = make_uint2(pk_lo(v.x, v.y), pk_lo(v.z, v.w));
}

// ---------------- LN(x) -> xn hi/lo ----------------
__global__ void ln_in(const float* __restrict__ xin, const float* __restrict__ g)
{
    __shared__ float red1[4], red2[4];
    size_t row = blockIdx.x;
    int tid = threadIdx.x;                 // 128
    float4 v = ((const float4*)(xin + row * NDIM))[tid];
    float s = v.x + v.y + v.z + v.w;
#pragma unroll
    for (int o = 16; o; o >>= 1) s += __shfl_xor_sync(0xffffffffu, s, o);
    if ((tid & 31) == 0) red1[tid >> 5] = s;
    __syncthreads();
    float mean = (red1[0] + red1[1] + red1[2] + red1[3]) * (1.0f / NDIM);
    float d0 = v.x - mean, d1 = v.y - mean, d2 = v.z - mean, d3 = v.w - mean;
    float ss = d0*d0 + d1*d1 + d2*d2 + d3*d3;
#pragma unroll
    for (int o = 16; o; o >>= 1) ss += __shfl_xor_sync(0xffffffffu, ss, o);
    if ((tid & 31) == 0) red2[tid >> 5] = ss;
    __syncthreads();
    float var = (red2[0] + red2[1] + red2[2] + red2[3]) * (1.0f / NDIM);
    float inv = rsqrtf(var + 1e-5f);
    float4 gv = ((const float4*)g)[tid];
    float o0 = d0*inv*gv.x, o1 = d1*inv*gv.y, o2 = d2*inv*gv.z, o3 = d3*inv*gv.w;
    *(uint2*)(g_xnh + row*NDIM + tid*4) = make_uint2(pk_hi(o0,o1), pk_hi(o2,o3));
    *(uint2*)(g_xnl + row*NDIM + tid*4) = make_uint2(pk_lo(o0,o1), pk_lo(o2,o3));
}

// ---------------- null kv ----------------
__global__ void fill_null(const float* __restrict__ nkv)
{
    int idx = blockIdx.x * 256 + threadIdx.x;
    if (idx >= BH * RD) return;
    int bh = idx / RD, rd = idx % RD, d = rd & 63;
    split1(nkv[d], &g_kh[(size_t)bh * NKV * RD + rd], &g_kl[(size_t)bh * NKV * RD + rd]);
    g_vf[(size_t)bh * NKV * RD + rd] = nkv[64 + d];
}

// ---------------- v transpose: [bh, j, rd] fp32 -> [bh, rd, j] hi/lo fp16 ----------------
__global__ void transpose_v()
{
    __shared__ float t[32][33];
    int z = blockIdx.z;
    int j0 = blockIdx.x * 32, rd0 = blockIdx.y * 32;
    const float* src = g_vf + (size_t)z * NKV * RD;
#pragma unroll
    for (int k = 0; k < 4; k++) {
        int jj = threadIdx.y + k * 8;
        int j = j0 + jj;
        t[jj][threadIdx.x] = (j < NKV) ? src[(size_t)j * RD + rd0 + threadIdx.x] : 0.f;
    }
    __syncthreads();
#pragma unroll
    for (int k = 0; k < 4; k++) {
        int dd = threadIdx.y + k * 8;
        float v = t[threadIdx.x][dd];
        size_t off = ((size_t)z * RD + rd0 + dd) * LDAT + j0 + threadIdx.x;
        split1(v, &g_vth[off], &g_vtl[off]);
    }
}

// ---------------- pb-relax softmax -> attn hi/lo fp16 (pad zeros) ----------------
__global__ void softmax_kernel()
{
    __shared__ float red[8];
    size_t gi = blockIdx.x;
    const float* p = g_sim + gi * LDSIM;
    __half* ah = g_ath + gi * LDAT;
    __half* al = g_atl + gi * LDAT;
    int tid = threadIdx.x;  // 256
    float vals[5];
    float mx = -1e30f;
#pragma unroll
    for (int it = 0; it < 5; it++) {
        int idx = tid + it * 256;
        float v = (idx < NKV) ? p[idx] : -1e30f;
        vals[it] = v; mx = fmaxf(mx, v);
    }
#pragma unroll
    for (int o = 16; o; o >>= 1) mx = fmaxf(mx, __shfl_xor_sync(0xffffffffu, mx, o));
    if ((tid & 31) == 0) red[tid >> 5] = mx;
    __syncthreads();
    float bm = red[0];
#pragma unroll
    for (int w = 1; w < 8; w++) bm = fmaxf(bm, red[w]);
    __syncthreads();
    float s = 0.f;
#pragma unroll
    for (int it = 0; it < 5; it++) {
        int idx = tid + it * 256;
        float e = (idx < NKV) ? expf((vals[it] - bm) * 128.0f) : 0.f;
        vals[it] = e; s += e;
    }
#pragma unroll
    for (int o = 16; o; o >>= 1) s += __shfl_xor_sync(0xffffffffu, s, o);
    if ((tid & 31) == 0) red[tid >> 5] = s;
    __syncthreads();
    float bs = red[0]+red[1]+red[2]+red[3]+red[4]+red[5]+red[6]+red[7];
    float inv = 1.0f / bs;
#pragma unroll
    for (int it = 0; it < 5; it++) {
        int idx = tid + it * 256;
        if (idx < LDAT) split1(vals[it] * inv, &ah[idx], &al[idx]);
    }
}

// ---------------- final LN ----------------
__global__ void ln_final(const float* __restrict__ g, float* __restrict__ yout)
{
    __shared__ float red1[4], red2[4];
    size_t row = blockIdx.x;
    int tid = threadIdx.x;
    float4 v = ((const float4*)(g_out + row * NDIM))[tid];
    float s = v.x + v.y + v.z + v.w;
#pragma unroll
    for (int o = 16; o; o >>= 1) s += __shfl_xor_sync(0xffffffffu, s, o);
    if ((tid & 31) == 0) red1[tid >> 5] = s;
    __syncthreads();
    float mean = (red1[0] + red1[1] + red1[2] + red1[3]) * (1.0f / NDIM);
    float d0 = v.x - mean, d1 = v.y - mean, d2 = v.z - mean, d3 = v.w - mean;
    float ss = d0*d0 + d1*d1 + d2*d2 + d3*d3;
#pragma unroll
    for (int o = 16; o; o >>= 1) ss += __shfl_xor_sync(0xffffffffu, ss, o);
    if ((tid & 31) == 0) red2[tid >> 5] = ss;
    __syncthreads();
    float var = (red2[0] + red2[1] + red2[2] + red2[3]) * (1.0f / NDIM);
    float inv = rsqrtf(var + 1e-5f);
    float4 gv = ((const float4*)g)[tid];
    ((float4*)(yout + row * NDIM))[tid] =
        make_float4(d0*inv*gv.x, d1*inv*gv.y, d2*inv*gv.z, d3*inv*gv.w);
}

// ---------------- launch ----------------
extern "C" void kernel_launch(void* const* d_in, const int* in_sizes, int n_in,
                              void* d_out, int out_size)
{
    const float* x        = (const float*)d_in[0];
    const float* context  = (const float*)d_in[1];
    const float* norm_g   = (const float*)d_in[2];
    const float* to_q_w   = (const float*)d_in[3];
    const float* to_kv_w  = (const float*)d_in[4];
    const float* null_kv  = (const float*)d_in[5];
    const float* to_out_w = (const float*)d_in[6];
    const float* out_ng   = (const float*)d_in[7];
    float* out = (float*)d_out;

    static bool attr_done = false;
    if (!attr_done) {
        cudaFuncSetAttribute(gemm_hmma<GQPROJ>,  cudaFuncAttributeMaxDynamicSharedMemorySize, GEMM_SMEM);
        cudaFuncSetAttribute(gemm_hmma<GKVPROJ>, cudaFuncAttributeMaxDynamicSharedMemorySize, GEMM_SMEM);
        cudaFuncSetAttribute(gemm_hmma<GSIM>,    cudaFuncAttributeMaxDynamicSharedMemorySize, GEMM_SMEM);
        cudaFuncSetAttribute(gemm_hmma<GAV>,     cudaFuncAttributeMaxDynamicSharedMemorySize, GEMM_SMEM);
        cudaFuncSetAttribute(gemm_hmma<GOPROJ>,  cudaFuncAttributeMaxDynamicSharedMemorySize, GEMM_SMEM);
        attr_done = true;
    }

    __half *wqh, *wql, *wkvh, *wkvl, *woh, *wol, *ctxh, *ctxl;
    cudaGetSymbolAddress((void**)&wqh,  g_wqh);  cudaGetSymbolAddress((void**)&wql,  g_wql);
    cudaGetSymbolAddress((void**)&wkvh, g_wkvh); cudaGetSymbolAddress((void**)&wkvl, g_wkvl);
    cudaGetSymbolAddress((void**)&woh,  g_woh);  cudaGetSymbolAddress((void**)&wol,  g_wol);
    cudaGetSymbolAddress((void**)&ctxh, g_ctxh); cudaGetSymbolAddress((void**)&ctxl, g_ctxl);

    // 0. conversions to hi/lo fp16
    conv_hilo<<<(NROWS*NDIM/4 + 255)/256, 256>>>(context, ctxh, ctxl, NROWS*NDIM/4);
    conv_hilo<<<(512*512/4 + 255)/256, 256>>>(to_q_w,  wqh,  wql,  512*512/4);
    conv_hilo<<<(1024*512/4 + 255)/256, 256>>>(to_kv_w, wkvh, wkvl, 1024*512/4);
    conv_hilo<<<(512*512/4 + 255)/256, 256>>>(to_out_w, woh,  wol,  512*512/4);
    // 1. xn = LN(x) -> hi/lo
    ln_in<<<NROWS, 128>>>(x, norm_g);
    // 2. q = xn @ Wq^T (unscaled) -> q hi/lo [bh,i,rd]
    gemm_hmma<GQPROJ><<<dim3(512/128, NROWS/128, 1), 256, GEMM_SMEM>>>();
    // 3. kv = ctx @ Wkv^T -> k hi/lo [bh,j+1,rd], v fp32 [bh,j+1,rd]
    gemm_hmma<GKVPROJ><<<dim3(1024/128, NROWS/128, 1), 256, GEMM_SMEM>>>();
    // 4. null kv row 0
    fill_null<<<(BH*RD + 255)/256, 256>>>(null_kv);
    // 5. sim = (q @ k^T) * scale -> fp32 [bh,i,1040]
    gemm_hmma<GSIM><<<dim3((NKV + 127)/128, NS/128, BH), 256, GEMM_SMEM>>>();
    // 6. softmax -> attn hi/lo [bh,i,1056] (zero pad)
    softmax_kernel<<<BH * NS, 256>>>();
    // 7. v transpose -> v_t hi/lo [bh,rd,1056] (zero pad)
    transpose_v<<<dim3(LDAT/32, RD/32, BH), dim3(32, 8)>>>();
    // 8. o = attn @ v -> o hi/lo [b,n,r,(h d)]
    gemm_hmma<GAV><<<dim3(RD/128, NS/128, BH), 256, GEMM_SMEM>>>();
    // 9. out = o @ Wout^T -> fp32 g_out
    gemm_hmma<GOPROJ><<<dim3(512/128, NROWS/128, 1), 256, GEMM_SMEM>>>();
    // 10. final LN -> d_out
    ln_final<<<NROWS, 128>>>(out_ng, out);
    (void)in_sizes; (void)n_in; (void)out_size;
}